// round 4
// baseline (speedup 1.0000x reference)
#include <cuda_runtime.h>
#include <math.h>

#define BB   8
#define HH   256
#define WW   256
#define HW   (HH*WW)

// Scratch (no device allocations allowed): per-row reduction partials + ticket.
__device__ float    g_part_pred[BB*HH];
__device__ float    g_part_w[BB*HH];
__device__ float    g_part_cnt[BB*HH];
__device__ unsigned g_ticket;     // zero-initialized; last block resets it to 0

// ---------------------------------------------------------------------------
// Fused kernel: one block per (b,h) row, one thread per pixel.
//  1. Vertical search, radius-chunked by 8: 16 independent predicated LDGs per
//     chunk (one L2 latency exposure instead of one per radius). Exact.
//  2. Horizontal lower envelope over BIG-padded smem, chunked by 4. Exact:
//     every candidate is a genuine j with reference-identical rounding, and
//     chunks stop only when r^2 >= both current minima.
//  3. Fused sigmoid/pred, weighting, block reduction, then last-block global
//     reduction (threadfence + ticket; deterministic summation order).
// ---------------------------------------------------------------------------
__global__ void __launch_bounds__(256) fused_kernel(
    const float* __restrict__ logits, const int* __restrict__ targets,
    float* __restrict__ out) {
    int row = blockIdx.x;          // b*256 + h
    int b   = row >> 8;
    int h   = row & 255;
    int w   = threadIdx.x;

    const int* tcol = targets + b * HW + w;   // column w of image b, stride WW
    int me = tcol[h * WW];

    // ---- vertical search: nearest 1 (r1) and nearest 0 (r0) along H ----
    int r1 = 256, r0 = 256;                    // 256 = "not found"
    if (me == 1) r1 = 0; else r0 = 0;
#pragma unroll 1
    for (int base = 0; base < HH; base += 8) {
        if (r1 < 256 && r0 < 256) break;
        unsigned m1 = 0, m0 = 0;
#pragma unroll
        for (int i = 1; i <= 8; i++) {         // 16 independent loads -> MLP
            int r  = base + i;
            int up = h - r, dn = h + r;
            int tu = (up >= 0) ? tcol[up * WW] : -1;
            int td = (dn < HH) ? tcol[dn * WW] : -1;
            unsigned bit = 1u << (i - 1);
            if (tu == 1 || td == 1) m1 |= bit;
            if (tu == 0 || td == 0) m0 |= bit;
        }
        if (r1 == 256 && m1) r1 = base + __ffs(m1);
        if (r0 == 256 && m0) r0 = base + __ffs(m0);
    }
    float d2p = (r1 < 256) ? (float)(r1 * r1) : 1e9f;   // dist^2 to nearest fg
    float d2n = (r0 < 256) ? (float)(r0 * r0) : 1e9f;   // dist^2 to nearest bg

    // ---- horizontal lower envelope with BIG-padded smem ----
    __shared__ float sp[3 * WW];
    __shared__ float sn[3 * WW];
    sp[w] = 1e9f; sp[2 * WW + w] = 1e9f;
    sn[w] = 1e9f; sn[2 * WW + w] = 1e9f;
    sp[WW + w] = d2p;
    sn[WW + w] = d2n;
    __syncthreads();

    float bp = d2p, bn = d2n;                  // r = 0 candidates
    const float* cp = sp + WW + w;
    const float* cn = sn + WW + w;
#pragma unroll 1
    for (int r = 1; r <= 253; r += 4) {        // chunks {r..r+3}, max offset 256
        float rr0f = (float)(r * r);
        if (rr0f >= bp && rr0f >= bn) break;
#pragma unroll
        for (int i = 0; i < 4; i++) {
            int   rj = r + i;
            float rr = (float)(rj * rj);
            // min(a,b)+rr == min(a+rr,b+rr): monotone rounding, bit-exact.
            bp = fminf(bp, fminf(cp[-rj], cp[rj]) + rr);
            bn = fminf(bn, fminf(cn[-rj], cn[rj]) + rr);
        }
    }

    // ---- loss terms ----
    // pred = softmax(logits,axis=1)[:,1] = sigmoid(l1 - l0)
    float l0 = logits[((b * 2 + 0) * HH + h) * WW + w];
    float l1 = logits[((b * 2 + 1) * HH + h) * WW + w];
    float pred = 1.0f / (1.0f + expf(l0 - l1));

    float sdt = sqrtf(bp) - sqrtf(bn);
    float wv  = pred * sdt;
    float cv  = (me == 1) ? 1.0f : 0.0f;

    // ---- deterministic block reduction (1 barrier) ----
    unsigned m = 0xFFFFFFFFu;
#pragma unroll
    for (int o = 16; o > 0; o >>= 1) {
        pred += __shfl_down_sync(m, pred, o);
        wv   += __shfl_down_sync(m, wv, o);
        cv   += __shfl_down_sync(m, cv, o);
    }
    __shared__ float rr0[8], rr1[8], rr2[8];
    if ((w & 31) == 0) {
        rr0[w >> 5] = pred; rr1[w >> 5] = wv; rr2[w >> 5] = cv;
    }
    __syncthreads();

    __shared__ bool s_last;
    if (w == 0) {
        float s0 = 0.f, s1 = 0.f, s2 = 0.f;
#pragma unroll
        for (int i = 0; i < 8; i++) { s0 += rr0[i]; s1 += rr1[i]; s2 += rr2[i]; }
        g_part_pred[row] = s0;
        g_part_w[row]    = s1;
        g_part_cnt[row]  = s2;
        __threadfence();                       // publish partials before ticket
        unsigned t = atomicAdd(&g_ticket, 1u);
        s_last = (t == (unsigned)(BB * HH - 1));
    }
    __syncthreads();
    if (!s_last) return;

    // ---- last block: global reduction (deterministic order) ----
    // 8 warps, one per batch; __ldcg bypasses L1 so freshly published
    // partials are read from L2.
    int wb   = w >> 5;
    int lane = w & 31;
    float s0 = 0.f, s1 = 0.f, s2 = 0.f;
#pragma unroll
    for (int i = 0; i < 8; i++) {
        int idx = wb * HH + lane + i * 32;
        s0 += __ldcg(&g_part_pred[idx]);
        s1 += __ldcg(&g_part_w[idx]);
        s2 += __ldcg(&g_part_cnt[idx]);
    }
#pragma unroll
    for (int o = 16; o > 0; o >>= 1) {
        s0 += __shfl_down_sync(m, s0, o);
        s1 += __shfl_down_sync(m, s1, o);
        s2 += __shfl_down_sync(m, s2, o);
    }
    __shared__ float pb[8];
    if (lane == 0) {
        float inv = 1.0f / (float)HW;
        float mean_pred = s0 * inv;
        float mean_w    = s1 * inv;
        float per_b;
        if (s2 == 0.0f)           per_b = mean_pred;
        else if (s2 == (float)HW) per_b = 1.0f - mean_pred;
        else                      per_b = mean_w;
        pb[wb] = per_b;
    }
    __syncthreads();
    if (w == 0) {
        float total = 0.f;
#pragma unroll
        for (int i = 0; i < BB; i++) total += pb[i];
        out[0] = total / (float)BB;
        g_ticket = 0;                          // reset for next graph replay
    }
}

extern "C" void kernel_launch(void* const* d_in, const int* in_sizes, int n_in,
                              void* d_out, int out_size) {
    const float* logits  = (const float*)d_in[0];
    const int*   targets = (const int*)d_in[1];
    float*       out     = (float*)d_out;

    fused_kernel<<<BB * HH, 256>>>(logits, targets, out);
}

// round 5
// speedup vs baseline: 1.1593x; 1.1593x over previous
#include <cuda_runtime.h>
#include <math.h>

#define BB   8
#define HH   256
#define WW   256
#define HW   (HH*WW)

// Scratch (no device allocations allowed): per-row reduction partials + ticket.
__device__ float    g_part_pred[BB*HH];
__device__ float    g_part_w[BB*HH];
__device__ float    g_part_cnt[BB*HH];
__device__ unsigned g_ticket;     // zero-initialized; last block resets it to 0

// ---------------------------------------------------------------------------
// Fused kernel: one block per (b,h) row, one thread per pixel.
//  1. Vertical serial early-exit search (issue-bound kernel: minimal instrs).
//     Border reads are CLAMPED, not predicated: a clamped read returns the
//     border pixel, whose flag was necessarily already set at the earlier
//     radius where it was legitimately visited -> provably a no-op.
//  2. Horizontal lower envelope over BIG-padded float2 smem, per-radius early
//     exit. Bit-exact vs reference brute force (monotone rounding, exact
//     integer r^2, candidates >= rr once rr >= current min).
//  3. Fast sigmoid, weighting, block reduction, last-block global reduction
//     (threadfence + ticket; deterministic summation order).
// ---------------------------------------------------------------------------
__global__ void __launch_bounds__(256) fused_kernel(
    const float* __restrict__ logits, const int* __restrict__ targets,
    float* __restrict__ out) {
    int row = blockIdx.x;          // b*256 + h
    int b   = row >> 8;
    int h   = row & 255;
    int w   = threadIdx.x;

    const int* tcol = targets + b * HW + w;   // column w of image b, stride WW
    float l0 = logits[((b * 2 + 0) * HH + h) * WW + w];
    float l1 = logits[((b * 2 + 1) * HH + h) * WW + w];
    int me = tcol[h * WW];

    // ---- vertical search: nearest 1 (r1) and nearest 0 (r0) along H ----
    int r1 = (me == 1) ? 0 : 256;
    int r0 = (me == 1) ? 256 : 0;
#pragma unroll 1
    for (int r = 1; r < HH; r++) {
        if ((r1 | r0) < 256) break;            // both resolved (r1,r0 <= 256)
        int iu = max(h - r, 0);
        int id = min(h + r, HH - 1);
        int tu = tcol[iu * WW];
        int td = tcol[id * WW];
        if (r1 == 256 && (tu | td))        r1 = r;   // some 1 at radius r
        if (r0 == 256 && (tu & td) == 0)   r0 = r;   // some 0 at radius r
    }
    float d2p = (r1 < 256) ? (float)(r1 * r1) : 1e9f;   // dist^2 to nearest fg
    float d2n = (r0 < 256) ? (float)(r0 * r0) : 1e9f;   // dist^2 to nearest bg

    // ---- horizontal lower envelope with BIG-padded float2 smem ----
    __shared__ float2 s[3 * WW];
    s[w]          = make_float2(1e9f, 1e9f);
    s[2 * WW + w] = make_float2(1e9f, 1e9f);
    s[WW + w]     = make_float2(d2p, d2n);
    __syncthreads();

    float bp = d2p, bn = d2n;                  // r = 0 candidates
    const float2* c = s + WW + w;
#pragma unroll 1
    for (int r = 1; r < WW; r++) {
        float rr = (float)(r * r);
        if (rr >= bp && rr >= bn) break;       // no larger radius can improve
        float2 a = c[-r];
        float2 d = c[r];
        // min(x,y)+rr == min(x+rr,y+rr): monotone rounding, bit-exact.
        bp = fminf(bp, fminf(a.x, d.x) + rr);
        bn = fminf(bn, fminf(a.y, d.y) + rr);
    }

    // ---- loss terms ----
    // pred = softmax(logits,axis=1)[:,1] = sigmoid(l1 - l0)
    float pred = __fdividef(1.0f, 1.0f + __expf(l0 - l1));

    float sdt = sqrtf(bp) - sqrtf(bn);
    float wv  = pred * sdt;
    float cv  = (float)me;                     // me in {0,1}

    // ---- deterministic block reduction (1 barrier) ----
    unsigned m = 0xFFFFFFFFu;
#pragma unroll
    for (int o = 16; o > 0; o >>= 1) {
        pred += __shfl_down_sync(m, pred, o);
        wv   += __shfl_down_sync(m, wv, o);
        cv   += __shfl_down_sync(m, cv, o);
    }
    __shared__ float rr0[8], rr1[8], rr2[8];
    if ((w & 31) == 0) {
        rr0[w >> 5] = pred; rr1[w >> 5] = wv; rr2[w >> 5] = cv;
    }
    __syncthreads();

    __shared__ bool s_last;
    if (w == 0) {
        float s0 = 0.f, s1 = 0.f, s2 = 0.f;
#pragma unroll
        for (int i = 0; i < 8; i++) { s0 += rr0[i]; s1 += rr1[i]; s2 += rr2[i]; }
        g_part_pred[row] = s0;
        g_part_w[row]    = s1;
        g_part_cnt[row]  = s2;
        __threadfence();                       // publish partials before ticket
        unsigned t = atomicAdd(&g_ticket, 1u);
        s_last = (t == (unsigned)(BB * HH - 1));
    }
    __syncthreads();
    if (!s_last) return;

    // ---- last block: global reduction (deterministic order) ----
    int wb   = w >> 5;
    int lane = w & 31;
    float s0 = 0.f, s1 = 0.f, s2 = 0.f;
#pragma unroll
    for (int i = 0; i < 8; i++) {
        int idx = wb * HH + lane + i * 32;
        s0 += __ldcg(&g_part_pred[idx]);
        s1 += __ldcg(&g_part_w[idx]);
        s2 += __ldcg(&g_part_cnt[idx]);
    }
#pragma unroll
    for (int o = 16; o > 0; o >>= 1) {
        s0 += __shfl_down_sync(m, s0, o);
        s1 += __shfl_down_sync(m, s1, o);
        s2 += __shfl_down_sync(m, s2, o);
    }
    __shared__ float pb[8];
    if (lane == 0) {
        float inv = 1.0f / (float)HW;
        float mean_pred = s0 * inv;
        float mean_w    = s1 * inv;
        float per_b;
        if (s2 == 0.0f)           per_b = mean_pred;
        else if (s2 == (float)HW) per_b = 1.0f - mean_pred;
        else                      per_b = mean_w;
        pb[wb] = per_b;
    }
    __syncthreads();
    if (w == 0) {
        float total = 0.f;
#pragma unroll
        for (int i = 0; i < BB; i++) total += pb[i];
        out[0] = total / (float)BB;
        g_ticket = 0;                          // reset for next graph replay
    }
}

extern "C" void kernel_launch(void* const* d_in, const int* in_sizes, int n_in,
                              void* d_out, int out_size) {
    const float* logits  = (const float*)d_in[0];
    const int*   targets = (const int*)d_in[1];
    float*       out     = (float*)d_out;

    fused_kernel<<<BB * HH, 256>>>(logits, targets, out);
}

// round 6
// speedup vs baseline: 1.2186x; 1.0512x over previous
#include <cuda_runtime.h>
#include <math.h>

#define BB   8
#define HH   256
#define WW   256
#define HW   (HH*WW)

// Scratch (no device allocations allowed): per-row reduction partials + ticket.
__device__ float    g_part_pred[BB*HH];
__device__ float    g_part_w[BB*HH];
__device__ float    g_part_cnt[BB*HH];
__device__ unsigned g_ticket;     // zero-initialized; last block resets it to 0

// ---------------------------------------------------------------------------
// Fused kernel: one block per (b,h) row, one thread per pixel.
//  1. Vertical search: UNCONDITIONAL batch r=1..4 (8 independent loads -> one
//     latency wall), resolve via bitmask+ffs; rare serial tail from r=5.
//     Clamped border reads only assert facts already present at a smaller or
//     equal radius bit, so ffs still returns the true minimum radius.
//  2. Horizontal envelope: UNCONDITIONAL batch r=1..4 over BIG-padded float2
//     smem (8 independent LDS.64 -> one wall), rare exact serial tail.
//     All candidates are genuine j's; min is order-independent; bit-exact.
//  3. Fast sigmoid, weighting, ballot-based count, block reduction,
//     last-block global reduction (threadfence + ticket; deterministic).
// ---------------------------------------------------------------------------
__global__ void __launch_bounds__(256) fused_kernel(
    const float* __restrict__ logits, const int* __restrict__ targets,
    float* __restrict__ out) {
    int row = blockIdx.x;          // b*256 + h
    int b   = row >> 8;
    int h   = row & 255;
    int w   = threadIdx.x;

    const int* tcol = targets + b * HW + w;   // column w of image b, stride WW
    float l0 = logits[((b * 2 + 0) * HH + h) * WW + w];
    float l1 = logits[((b * 2 + 1) * HH + h) * WW + w];
    int me = tcol[h * WW];

    // ---- vertical search: batched prefix r=1..4 ----
    int a1 = tcol[max(h - 1, 0) * WW], e1 = tcol[min(h + 1, HH - 1) * WW];
    int a2 = tcol[max(h - 2, 0) * WW], e2 = tcol[min(h + 2, HH - 1) * WW];
    int a3 = tcol[max(h - 3, 0) * WW], e3 = tcol[min(h + 3, HH - 1) * WW];
    int a4 = tcol[max(h - 4, 0) * WW], e4 = tcol[min(h + 4, HH - 1) * WW];

    unsigned m1 = (unsigned)((a1 | e1) | ((a2 | e2) << 1) |
                             ((a3 | e3) << 2) | ((a4 | e4) << 3));
    unsigned m0 = (unsigned)(((a1 & e1) ^ 1) | (((a2 & e2) ^ 1) << 1) |
                             (((a3 & e3) ^ 1) << 2) | (((a4 & e4) ^ 1) << 3));

    int r1 = (me == 1) ? 0 : (m1 ? __ffs(m1) : 256);
    int r0 = (me == 0) ? 0 : (m0 ? __ffs(m0) : 256);

    if ((r1 | r0) >= 256) {                    // rare tail: serial exact search
#pragma unroll 1
        for (int r = 5; r < HH; r++) {
            if ((r1 | r0) < 256) break;
            int tu = tcol[max(h - r, 0) * WW];
            int td = tcol[min(h + r, HH - 1) * WW];
            if (r1 == 256 && (tu | td))      r1 = r;
            if (r0 == 256 && (tu & td) == 0) r0 = r;
        }
    }
    float d2p = (r1 < 256) ? (float)(r1 * r1) : 1e9f;   // dist^2 to nearest fg
    float d2n = (r0 < 256) ? (float)(r0 * r0) : 1e9f;   // dist^2 to nearest bg

    // ---- horizontal lower envelope with BIG-padded float2 smem ----
    __shared__ float2 s[3 * WW];
    s[w]          = make_float2(1e9f, 1e9f);
    s[2 * WW + w] = make_float2(1e9f, 1e9f);
    s[WW + w]     = make_float2(d2p, d2n);
    __syncthreads();

    const float2* c = s + WW + w;
    float bp = d2p, bn = d2n;                  // r = 0 candidates

    // batched prefix r=1..4 (8 independent LDS.64, one latency wall)
    float2 L1 = c[-1], R1 = c[1];
    float2 L2 = c[-2], R2 = c[2];
    float2 L3 = c[-3], R3 = c[3];
    float2 L4 = c[-4], R4 = c[4];
    bp = fminf(bp, fminf(L1.x, R1.x) + 1.0f);  bn = fminf(bn, fminf(L1.y, R1.y) + 1.0f);
    bp = fminf(bp, fminf(L2.x, R2.x) + 4.0f);  bn = fminf(bn, fminf(L2.y, R2.y) + 4.0f);
    bp = fminf(bp, fminf(L3.x, R3.x) + 9.0f);  bn = fminf(bn, fminf(L3.y, R3.y) + 9.0f);
    bp = fminf(bp, fminf(L4.x, R4.x) + 16.0f); bn = fminf(bn, fminf(L4.y, R4.y) + 16.0f);

    if (fmaxf(bp, bn) > 25.0f) {               // rare tail: exact serial loop
#pragma unroll 1
        for (int r = 5; r < WW; r++) {
            float rr = (float)(r * r);
            if (rr >= bp && rr >= bn) break;
            float2 a = c[-r];
            float2 d = c[r];
            bp = fminf(bp, fminf(a.x, d.x) + rr);
            bn = fminf(bn, fminf(a.y, d.y) + rr);
        }
    }

    // ---- loss terms ----
    // pred = softmax(logits,axis=1)[:,1] = sigmoid(l1 - l0)
    float pred = __fdividef(1.0f, 1.0f + __expf(l0 - l1));

    float sdt = sqrtf(bp) - sqrtf(bn);
    float wv  = pred * sdt;

    // ---- deterministic block reduction (1 barrier) ----
    unsigned m = 0xFFFFFFFFu;
    float cv = (float)__popc(__ballot_sync(m, me == 1));   // warp fg count
#pragma unroll
    for (int o = 16; o > 0; o >>= 1) {
        pred += __shfl_down_sync(m, pred, o);
        wv   += __shfl_down_sync(m, wv, o);
    }
    __shared__ float rr0[8], rr1[8], rr2[8];
    if ((w & 31) == 0) {
        rr0[w >> 5] = pred; rr1[w >> 5] = wv; rr2[w >> 5] = cv;
    }
    __syncthreads();

    __shared__ bool s_last;
    if (w == 0) {
        float s0 = 0.f, s1 = 0.f, s2 = 0.f;
#pragma unroll
        for (int i = 0; i < 8; i++) { s0 += rr0[i]; s1 += rr1[i]; s2 += rr2[i]; }
        g_part_pred[row] = s0;
        g_part_w[row]    = s1;
        g_part_cnt[row]  = s2;
        __threadfence();                       // publish partials before ticket
        unsigned t = atomicAdd(&g_ticket, 1u);
        s_last = (t == (unsigned)(BB * HH - 1));
    }
    __syncthreads();
    if (!s_last) return;

    // ---- last block: global reduction (deterministic order) ----
    int wb   = w >> 5;
    int lane = w & 31;
    float s0 = 0.f, s1 = 0.f, s2 = 0.f;
#pragma unroll
    for (int i = 0; i < 8; i++) {
        int idx = wb * HH + lane + i * 32;
        s0 += __ldcg(&g_part_pred[idx]);
        s1 += __ldcg(&g_part_w[idx]);
        s2 += __ldcg(&g_part_cnt[idx]);
    }
#pragma unroll
    for (int o = 16; o > 0; o >>= 1) {
        s0 += __shfl_down_sync(m, s0, o);
        s1 += __shfl_down_sync(m, s1, o);
        s2 += __shfl_down_sync(m, s2, o);
    }
    __shared__ float pb[8];
    if (lane == 0) {
        float inv = 1.0f / (float)HW;
        float mean_pred = s0 * inv;
        float mean_w    = s1 * inv;
        float per_b;
        if (s2 == 0.0f)           per_b = mean_pred;
        else if (s2 == (float)HW) per_b = 1.0f - mean_pred;
        else                      per_b = mean_w;
        pb[wb] = per_b;
    }
    __syncthreads();
    if (w == 0) {
        float total = 0.f;
#pragma unroll
        for (int i = 0; i < BB; i++) total += pb[i];
        out[0] = total / (float)BB;
        g_ticket = 0;                          // reset for next graph replay
    }
}

extern "C" void kernel_launch(void* const* d_in, const int* in_sizes, int n_in,
                              void* d_out, int out_size) {
    const float* logits  = (const float*)d_in[0];
    const int*   targets = (const int*)d_in[1];
    float*       out     = (float*)d_out;

    fused_kernel<<<BB * HH, 256>>>(logits, targets, out);
}

// round 8
// speedup vs baseline: 1.3610x; 1.1169x over previous
#include <cuda_runtime.h>
#include <math.h>

#define BB   8
#define HH   256
#define WW   256
#define HW   (HH*WW)
#define RPB  4
#define NBLK (BB*HH/RPB)   // 512 blocks, 64 per image

// Scratch (no device allocations allowed): per-block partials + ticket.
__device__ float    g_pp[NBLK];
__device__ float    g_pw[NBLK];
__device__ float    g_pc[NBLK];
__device__ unsigned g_ticket;     // zero-init; last block resets to 0

// ---------------------------------------------------------------------------
// Fused kernel: one block per 4 rows (same image), one thread per column.
//  - 12 target rows loaded once into REGISTERS; all 4 vertical r=1..4 prefix
//    masks computed from them (exact; clamped bits only re-assert facts from
//    smaller radii, the true minimal radius always sets its own bit).
//  - Rare vertical tail r>=5 straight from gmem (exact serial search).
//  - 4 independent horizontal envelopes (prefix r=1..4 over +-8-padded float2
//    smem, bounds-checked exact serial tail). Bit-exact vs reference.
//  - One reduction for all 4 rows (only per-batch sums are needed).
//  - Last-block global reduction (threadfence + ticket; deterministic).
// ---------------------------------------------------------------------------
__global__ void __launch_bounds__(256) fused_kernel(
    const float* __restrict__ logits, const int* __restrict__ targets,
    float* __restrict__ out) {
    int blk = blockIdx.x;          // 0..511
    int b   = blk >> 6;            // image
    int h0  = (blk & 63) * RPB;    // first of 4 rows
    int w   = threadIdx.x;

    const int* tcol = targets + b * HW + w;   // column w, stride WW

    // ---- 12 clamped target rows -> registers ----
    int t[RPB + 8];
#pragma unroll
    for (int j = 0; j < RPB + 8; j++) {
        int hh = min(max(h0 - 4 + j, 0), HH - 1);
        t[j] = tcol[hh * WW];
    }

    __shared__ float2 srow[RPB][WW + 16];     // +-8 BIG pads
    if (w < 8) {
#pragma unroll
        for (int i = 0; i < RPB; i++) {
            srow[i][w]          = make_float2(1e9f, 1e9f);
            srow[i][WW + 8 + w] = make_float2(1e9f, 1e9f);
        }
    }

    float d2p_[RPB], d2n_[RPB];
    int   me_[RPB];

#pragma unroll
    for (int i = 0; i < RPB; i++) {
        int hl = i + 4;
        int me = t[hl];
        me_[i] = me;
        unsigned m1 = 0, m0 = 0;
#pragma unroll
        for (int r = 1; r <= 4; r++) {
            int o = t[hl - r] | t[hl + r];
            int a = t[hl - r] & t[hl + r];
            m1 |= (unsigned)o << (r - 1);
            m0 |= (unsigned)(a ^ 1) << (r - 1);
        }
        int r1 = me        ? 0 : (m1 ? __ffs(m1) : 256);
        int r0 = (me == 0) ? 0 : (m0 ? __ffs(m0) : 256);

        if ((r1 | r0) >= 256) {               // rare exact tail from gmem
            int h = h0 + i;
#pragma unroll 1
            for (int r = 5; r < HH; r++) {
                if ((r1 | r0) < 256) break;
                int tu = tcol[max(h - r, 0) * WW];
                int td = tcol[min(h + r, HH - 1) * WW];
                if (r1 == 256 && (tu | td))      r1 = r;
                if (r0 == 256 && (tu & td) == 0) r0 = r;
            }
        }
        d2p_[i] = (r1 < 256) ? (float)(r1 * r1) : 1e9f;
        d2n_[i] = (r0 < 256) ? (float)(r0 * r0) : 1e9f;
        srow[i][8 + w] = make_float2(d2p_[i], d2n_[i]);
    }
    __syncthreads();

    float accP = 0.f, accW = 0.f;
    int   accC = 0;

#pragma unroll
    for (int i = 0; i < RPB; i++) {
        const float2* c = &srow[i][8 + w];
        float bp = d2p_[i], bn = d2n_[i];

        float2 L1 = c[-1], R1 = c[1];
        float2 L2 = c[-2], R2 = c[2];
        float2 L3 = c[-3], R3 = c[3];
        float2 L4 = c[-4], R4 = c[4];
        bp = fminf(bp, fminf(L1.x, R1.x) + 1.0f);  bn = fminf(bn, fminf(L1.y, R1.y) + 1.0f);
        bp = fminf(bp, fminf(L2.x, R2.x) + 4.0f);  bn = fminf(bn, fminf(L2.y, R2.y) + 4.0f);
        bp = fminf(bp, fminf(L3.x, R3.x) + 9.0f);  bn = fminf(bn, fminf(L3.y, R3.y) + 9.0f);
        bp = fminf(bp, fminf(L4.x, R4.x) + 16.0f); bn = fminf(bn, fminf(L4.y, R4.y) + 16.0f);

        if (fmaxf(bp, bn) > 25.0f) {          // rare exact serial tail
#pragma unroll 1
            for (int r = 5; r < WW; r++) {
                float rr = (float)(r * r);
                if (rr >= bp && rr >= bn) break;
                if (w - r >= 0) {
                    float2 a = srow[i][8 + w - r];
                    bp = fminf(bp, a.x + rr); bn = fminf(bn, a.y + rr);
                }
                if (w + r < WW) {
                    float2 d = srow[i][8 + w + r];
                    bp = fminf(bp, d.x + rr); bn = fminf(bn, d.y + rr);
                }
            }
        }

        int h = h0 + i;
        float l0 = logits[((b * 2 + 0) * HH + h) * WW + w];
        float l1 = logits[((b * 2 + 1) * HH + h) * WW + w];
        float pred = __fdividef(1.0f, 1.0f + __expf(l0 - l1));

        accP += pred;
        accW += pred * (sqrtf(bp) - sqrtf(bn));
        accC += me_[i];
    }

    // ---- single deterministic block reduction for all 4 rows ----
    unsigned m = 0xFFFFFFFFu;
    float cv = (float)accC;
#pragma unroll
    for (int o = 16; o > 0; o >>= 1) {
        accP += __shfl_down_sync(m, accP, o);
        accW += __shfl_down_sync(m, accW, o);
        cv   += __shfl_down_sync(m, cv, o);
    }
    __shared__ float rr0[8], rr1[8], rr2[8];
    if ((w & 31) == 0) {
        rr0[w >> 5] = accP; rr1[w >> 5] = accW; rr2[w >> 5] = cv;
    }
    __syncthreads();

    __shared__ bool s_last;
    if (w == 0) {
        float s0 = 0.f, s1 = 0.f, s2 = 0.f;
#pragma unroll
        for (int i = 0; i < 8; i++) { s0 += rr0[i]; s1 += rr1[i]; s2 += rr2[i]; }
        g_pp[blk] = s0;
        g_pw[blk] = s1;
        g_pc[blk] = s2;
        __threadfence();
        unsigned tk = atomicAdd(&g_ticket, 1u);
        s_last = (tk == (unsigned)(NBLK - 1));
    }
    __syncthreads();
    if (!s_last) return;

    // ---- last block: global reduction (deterministic order) ----
    int wb   = w >> 5;             // batch handled by this warp
    int lane = w & 31;
    int base = wb * 64;
    float s0 = __ldcg(&g_pp[base + lane]) + __ldcg(&g_pp[base + 32 + lane]);
    float s1 = __ldcg(&g_pw[base + lane]) + __ldcg(&g_pw[base + 32 + lane]);
    float s2 = __ldcg(&g_pc[base + lane]) + __ldcg(&g_pc[base + 32 + lane]);
#pragma unroll
    for (int o = 16; o > 0; o >>= 1) {
        s0 += __shfl_down_sync(m, s0, o);
        s1 += __shfl_down_sync(m, s1, o);
        s2 += __shfl_down_sync(m, s2, o);
    }
    __shared__ float pb[8];
    if (lane == 0) {
        float inv = 1.0f / (float)HW;
        float mean_pred = s0 * inv;
        float mean_w    = s1 * inv;
        float per_b;
        if (s2 == 0.0f)           per_b = mean_pred;
        else if (s2 == (float)HW) per_b = 1.0f - mean_pred;
        else                      per_b = mean_w;
        pb[wb] = per_b;
    }
    __syncthreads();
    if (w == 0) {
        float total = 0.f;
#pragma unroll
        for (int i = 0; i < BB; i++) total += pb[i];
        out[0] = total / (float)BB;
        g_ticket = 0;                          // reset for next graph replay
    }
}

extern "C" void kernel_launch(void* const* d_in, const int* in_sizes, int n_in,
                              void* d_out, int out_size) {
    const float* logits  = (const float*)d_in[0];
    const int*   targets = (const int*)d_in[1];
    float*       out     = (float*)d_out;

    fused_kernel<<<NBLK, 256>>>(logits, targets, out);
}